// round 1
// baseline (speedup 1.0000x reference)
#include <cuda_runtime.h>
#include <math.h>

#define THREADS 256

// 240 E8 roots, reference enumeration order, computed per launch (deterministic).
__device__ float g_roots[240 * 8];

__global__ void init_roots_kernel() {
    int idx = blockIdx.x * blockDim.x + threadIdx.x;
    if (idx >= 240) return;
    float v[8];
#pragma unroll
    for (int k = 0; k < 8; k++) v[k] = 0.f;
    if (idx < 112) {
        int p = idx >> 2, sb = idx & 3;
        int i = 0, rem = p;
        while (rem >= 7 - i) { rem -= (7 - i); i++; }
        int j = i + 1 + rem;
        v[i] = (sb & 2) ? -1.f : 1.f;
        v[j] = (sb & 1) ? -1.f : 1.f;
    } else {
        int b = (idx - 112) << 1;
        if (__popc(b) & 1) b |= 1;          // restore even-parity member of the pair
#pragma unroll
        for (int k = 0; k < 8; k++) v[k] = ((b >> k) & 1) ? -0.5f : 0.5f;
    }
#pragma unroll
    for (int k = 0; k < 8; k++) g_roots[idx * 8 + k] = v[k];
}

__device__ __forceinline__ float gelu_exact(float x) {
    return 0.5f * x * (1.0f + erff(x * 0.70710678118654752f));
}

__global__ __launch_bounds__(THREADS) void rcpl_kernel(
    const float* __restrict__ obs,   const float* __restrict__ w1, const float* __restrict__ b1,
    const float* __restrict__ w2,    const float* __restrict__ b2,
    const float* __restrict__ le,    const float* __restrict__ bctl, const float* __restrict__ rctl,
    const float* __restrict__ bc,    const float* __restrict__ ld,
    const float* __restrict__ rw1,   const float* __restrict__ rb1,
    const float* __restrict__ rw2,   const float* __restrict__ rb2,
    const float* __restrict__ rgate, float* __restrict__ out, int B)
{
    extern __shared__ float sm[];
    float* w1S   = sm;             // 448   [l*14+k]
    float* b1S   = w1S + 448;      // 32
    float* w2TS  = b1S + 32;       // 256   [l*8+j] (transposed)
    float* b2S   = w2TS + 256;     // 8
    float* rootsS= b2S + 8;        // 1920  [j*8+k]
    float* kS    = rootsS + 1920;  // 240   bc[j] + 2C
    float* embS  = kS + 240;       // 13440 [j*56+c] (emb0 || base_ctrl)
    float* rw1S  = embS + 13440;   // 2704  [c*52+k]
    float* rb1S  = rw1S + 2704;    // 52
    float* rw2TS = rb1S + 52;      // 2704  [c*52+k2] (transposed)
    float* rb2S  = rw2TS + 2704;   // 52
    // total 21856 floats = 87424 bytes

    const float C = 1.0201941611100342f;   // log2(e)/sqrt(2)

    const int t = threadIdx.x;
    for (int i = t; i < 448;  i += THREADS) w1S[i] = w1[i];
    for (int i = t; i < 32;   i += THREADS) b1S[i] = b1[i];
    for (int i = t; i < 256;  i += THREADS) { int l = i >> 3, j = i & 7; w2TS[i] = w2[j * 32 + l]; }
    for (int i = t; i < 8;    i += THREADS) b2S[i] = b2[i];
    for (int i = t; i < 1920; i += THREADS) rootsS[i] = g_roots[i];
    for (int i = t; i < 240;  i += THREADS) kS[i] = bc[i] + 2.0f * C;
    for (int i = t; i < 240 * 56; i += THREADS) {
        int r = i / 56, c = i - r * 56;
        embS[i] = (c < 52) ? le[r * 52 + c] : bctl[r * 4 + (c - 52)];
    }
    for (int i = t; i < 2704; i += THREADS) rw1S[i] = rw1[i];
    for (int i = t; i < 52;   i += THREADS) rb1S[i] = rb1[i];
    for (int i = t; i < 2704; i += THREADS) { int c = i / 52, k = i - c * 52; rw2TS[i] = rw2[k * 52 + c]; }
    for (int i = t; i < 52;   i += THREADS) rb2S[i] = rb2[i];
    __syncthreads();

    int row = blockIdx.x * THREADS + t;
    if (row >= B) return;

    // ---------------- projection: 14 -> 32 -> 8, fused (no h[32] storage) ----------------
    float x[14];
    {
        const float2* po = reinterpret_cast<const float2*>(obs + (size_t)row * 14);
#pragma unroll
        for (int k = 0; k < 7; k++) { float2 v = po[k]; x[2 * k] = v.x; x[2 * k + 1] = v.y; }
    }
    float q[8];
#pragma unroll
    for (int j = 0; j < 8; j++) q[j] = b2S[j];
#pragma unroll 2
    for (int l = 0; l < 32; l++) {
        float a0 = b1S[l], a1 = 0.f;
        const float2* wr = reinterpret_cast<const float2*>(&w1S[l * 14]);
#pragma unroll
        for (int k = 0; k < 7; k++) { float2 w = wr[k]; a0 = fmaf(x[2 * k], w.x, a0); a1 = fmaf(x[2 * k + 1], w.y, a1); }
        float g = gelu_exact(a0 + a1);
        const float4* wt = reinterpret_cast<const float4*>(&w2TS[l * 8]);
        float4 u0 = wt[0], u1 = wt[1];
        q[0] = fmaf(g, u0.x, q[0]); q[1] = fmaf(g, u0.y, q[1]);
        q[2] = fmaf(g, u0.z, q[2]); q[3] = fmaf(g, u0.w, q[3]);
        q[4] = fmaf(g, u1.x, q[4]); q[5] = fmaf(g, u1.y, q[5]);
        q[6] = fmaf(g, u1.z, q[6]); q[7] = fmaf(g, u1.w, q[7]);
    }
    // L2-normalize to length sqrt(2)
    {
        float n2 = 0.f;
#pragma unroll
        for (int j = 0; j < 8; j++) n2 = fmaf(q[j], q[j], n2);
        float sc = 1.4142135623730951f / fmaxf(sqrtf(n2), 1e-12f);
#pragma unroll
        for (int j = 0; j < 8; j++) q[j] *= sc;
    }

    // ------- fused pass over 240 roots: dot + level-0 argmax + unnormalized softmax GEMM -------
    // logits*log2e = dot*C - bc[j]; constant shift 2C is valid since dot <= |q||r| = 2.
    float acc[56];
#pragma unroll
    for (int c = 0; c < 56; c++) acc[c] = 0.f;
    float S = 0.f, bestdot = -1e30f;
    int bestj = 0;
    for (int j = 0; j < 240; j++) {
        const float4* rp = reinterpret_cast<const float4*>(&rootsS[j * 8]);
        float4 r0 = rp[0], r1 = rp[1];
        float d0 = fmaf(q[1], r0.y, q[0] * r0.x);
        d0 = fmaf(q[2], r0.z, d0); d0 = fmaf(q[3], r0.w, d0);
        float d1 = fmaf(q[5], r1.y, q[4] * r1.x);
        d1 = fmaf(q[6], r1.z, d1); d1 = fmaf(q[7], r1.w, d1);
        float dot = d0 + d1;
        if (dot > bestdot) { bestdot = dot; bestj = j; }   // strict > : first index on ties
        float e = exp2f(fmaf(dot, C, -kS[j]));
        S += e;
        const float4* ep = reinterpret_cast<const float4*>(&embS[j * 56]);
#pragma unroll
        for (int c4 = 0; c4 < 14; c4++) {
            float4 ev = ep[c4];
            acc[4 * c4 + 0] = fmaf(e, ev.x, acc[4 * c4 + 0]);
            acc[4 * c4 + 1] = fmaf(e, ev.y, acc[4 * c4 + 1]);
            acc[4 * c4 + 2] = fmaf(e, ev.z, acc[4 * c4 + 2]);
            acc[4 * c4 + 3] = fmaf(e, ev.w, acc[4 * c4 + 3]);
        }
    }
    {
        float invS = 1.0f / S;
#pragma unroll
        for (int c = 0; c < 56; c++) acc[c] *= invS;
    }

    // ---------------- residual E8 quantization, analytic nearest-root decode ----------------
    float res[8];
    {
        const float4* rp = reinterpret_cast<const float4*>(&rootsS[bestj * 8]);
        float4 r0 = rp[0], r1 = rp[1];
        res[0] = fmaf(-2.f, r0.x, q[0]); res[1] = fmaf(-2.f, r0.y, q[1]);
        res[2] = fmaf(-2.f, r0.z, q[2]); res[3] = fmaf(-2.f, r0.w, q[3]);
        res[4] = fmaf(-2.f, r1.x, q[4]); res[5] = fmaf(-2.f, r1.y, q[5]);
        res[6] = fmaf(-2.f, r1.z, q[6]); res[7] = fmaf(-2.f, r1.w, q[7]);
    }
    float decay = expf(ld[0]);
    float invd = 1.0f / decay;
    float s = 2.0f, g = 1.0f;
    for (int lev = 1; lev < 8; lev++) {
        s *= invd; g *= invd;
        float a[8];
#pragma unroll
        for (int k = 0; k < 8; k++) a[k] = fabsf(res[k]);
        // top-2 |components| (lowest index on ties)
        int m1 = 0; float v1 = a[0];
#pragma unroll
        for (int k = 1; k < 8; k++) if (a[k] > v1) { v1 = a[k]; m1 = k; }
        int m2 = -1; float v2 = -1.f;
#pragma unroll
        for (int k = 0; k < 8; k++) if (k != m1 && a[k] > v2) { v2 = a[k]; m2 = k; }
        float valA = v1 + v2;
        float sum = 0.f;
#pragma unroll
        for (int k = 0; k < 8; k++) sum += a[k];
        int mask = 0;
#pragma unroll
        for (int k = 0; k < 8; k++) mask |= (res[k] < 0.f) ? (1 << k) : 0;
        int km = 0; float vm = a[0];
#pragma unroll
        for (int k = 1; k < 8; k++) if (a[k] < vm) { vm = a[k]; km = k; }
        int par = __popc(mask) & 1;
        float valB = 0.5f * sum - (par ? vm : 0.f);
        int idx;
        if (valA >= valB) {            // tie -> type A (lower enumeration index)
            int i = (m1 < m2) ? m1 : m2, jj = (m1 < m2) ? m2 : m1;
            int bi = (res[i] < 0.f) ? 1 : 0, bj = (res[jj] < 0.f) ? 1 : 0;
            idx = (7 * i - (i * (i - 1)) / 2 + (jj - i - 1)) * 4 + bi * 2 + bj;
            float di = bi ? -s : s, dj = bj ? -s : s;
#pragma unroll
            for (int k = 0; k < 8; k++) {
                if (k == i)  res[k] -= di;
                if (k == jj) res[k] -= dj;
            }
        } else {
            int bits = par ? (mask ^ (1 << km)) : mask;
            idx = 112 + (bits >> 1);
            float hs = 0.5f * s;
#pragma unroll
            for (int k = 0; k < 8; k++) res[k] -= ((bits >> k) & 1) ? -hs : hs;
        }
        // gather-accumulate level contribution (L2-resident tables)
        const float4* ep = reinterpret_cast<const float4*>(le + ((size_t)lev * 240 + idx) * 52);
#pragma unroll
        for (int c4 = 0; c4 < 13; c4++) {
            float4 ev = __ldg(&ep[c4]);
            acc[4 * c4 + 0] = fmaf(g, ev.x, acc[4 * c4 + 0]);
            acc[4 * c4 + 1] = fmaf(g, ev.y, acc[4 * c4 + 1]);
            acc[4 * c4 + 2] = fmaf(g, ev.z, acc[4 * c4 + 2]);
            acc[4 * c4 + 3] = fmaf(g, ev.w, acc[4 * c4 + 3]);
        }
        float4 cv = __ldg(reinterpret_cast<const float4*>(rctl + ((size_t)(lev - 1) * 240 + idx) * 4));
        acc[52] = fmaf(g, cv.x, acc[52]); acc[53] = fmaf(g, cv.y, acc[53]);
        acc[54] = fmaf(g, cv.z, acc[54]); acc[55] = fmaf(g, cv.w, acc[55]);
    }

    // ---------------- gated refine MLP (fused: no hidden[] storage) ----------------
    float r2a[52];
#pragma unroll
    for (int k = 0; k < 52; k++) r2a[k] = 0.f;
#pragma unroll 2
    for (int c = 0; c < 52; c++) {
        float p0 = rb1S[c], p1 = 0.f, p2 = 0.f, p3 = 0.f;
        const float4* wr = reinterpret_cast<const float4*>(&rw1S[c * 52]);
#pragma unroll
        for (int k4 = 0; k4 < 13; k4++) {
            float4 w = wr[k4];
            p0 = fmaf(acc[4 * k4 + 0], w.x, p0);
            p1 = fmaf(acc[4 * k4 + 1], w.y, p1);
            p2 = fmaf(acc[4 * k4 + 2], w.z, p2);
            p3 = fmaf(acc[4 * k4 + 3], w.w, p3);
        }
        float gv = gelu_exact((p0 + p1) + (p2 + p3));
        const float4* w2r = reinterpret_cast<const float4*>(&rw2TS[c * 52]);
#pragma unroll
        for (int k4 = 0; k4 < 13; k4++) {
            float4 w = w2r[k4];
            r2a[4 * k4 + 0] = fmaf(gv, w.x, r2a[4 * k4 + 0]);
            r2a[4 * k4 + 1] = fmaf(gv, w.y, r2a[4 * k4 + 1]);
            r2a[4 * k4 + 2] = fmaf(gv, w.z, r2a[4 * k4 + 2]);
            r2a[4 * k4 + 3] = fmaf(gv, w.w, r2a[4 * k4 + 3]);
        }
    }
    {
        float gate = 1.0f / (1.0f + expf(-rgate[0]));
#pragma unroll
        for (int c = 0; c < 52; c++) acc[c] = fmaf(gate, r2a[c] + rb2S[c], acc[c]);
    }

    // ---------------- store [56] ----------------
    float4* op = reinterpret_cast<float4*>(out + (size_t)row * 56);
#pragma unroll
    for (int c4 = 0; c4 < 14; c4++) {
        float4 v;
        v.x = acc[4 * c4 + 0]; v.y = acc[4 * c4 + 1];
        v.z = acc[4 * c4 + 2]; v.w = acc[4 * c4 + 3];
        op[c4] = v;
    }
}

extern "C" void kernel_launch(void* const* d_in, const int* in_sizes, int n_in,
                              void* d_out, int out_size) {
    const float* obs   = (const float*)d_in[0];
    const float* w1    = (const float*)d_in[1];
    const float* b1    = (const float*)d_in[2];
    const float* w2    = (const float*)d_in[3];
    const float* b2    = (const float*)d_in[4];
    const float* le    = (const float*)d_in[5];
    const float* bctl  = (const float*)d_in[6];
    const float* rctl  = (const float*)d_in[7];
    const float* bc    = (const float*)d_in[8];
    const float* ld    = (const float*)d_in[9];
    const float* rw1   = (const float*)d_in[10];
    const float* rb1   = (const float*)d_in[11];
    const float* rw2   = (const float*)d_in[12];
    const float* rb2   = (const float*)d_in[13];
    const float* rgate = (const float*)d_in[14];
    float* out = (float*)d_out;

    int B = in_sizes[0] / 14;
    const int smem = 21856 * 4;
    cudaFuncSetAttribute(rcpl_kernel, cudaFuncAttributeMaxDynamicSharedMemorySize, smem);

    init_roots_kernel<<<1, 256>>>();
    rcpl_kernel<<<(B + THREADS - 1) / THREADS, THREADS, smem>>>(
        obs, w1, b1, w2, b2, le, bctl, rctl, bc, ld, rw1, rb1, rw2, rb2, rgate, out, B);
}

// round 3
// speedup vs baseline: 1.1040x; 1.1040x over previous
#include <cuda_runtime.h>
#include <math.h>

#define THREADS 256

// ---------------- constant bank: exactly 64KB ----------------
// [0      : 13440)  embcat  [j*56 + c]  (level0 emb || base_ctrl)
// [13440  : 13680)  kS      [j]         (bc[j] + 2*C, base-2 exponent offset)
// [13680  : 16384)  rw1     [c*52 + k]
__constant__ float c_tab[16384];

__device__ float g_stage[16384];
__device__ float g_roots[240 * 8];

__global__ void init_roots_kernel() {
    int idx = blockIdx.x * blockDim.x + threadIdx.x;
    if (idx >= 240) return;
    float v[8];
#pragma unroll
    for (int k = 0; k < 8; k++) v[k] = 0.f;
    if (idx < 112) {
        int p = idx >> 2, sb = idx & 3;
        int i = 0, rem = p;
        while (rem >= 7 - i) { rem -= (7 - i); i++; }
        int j = i + 1 + rem;
        v[i] = (sb & 2) ? -1.f : 1.f;
        v[j] = (sb & 1) ? -1.f : 1.f;
    } else {
        int b = (idx - 112) << 1;
        if (__popc(b) & 1) b |= 1;          // even-parity member of the pair
#pragma unroll
        for (int k = 0; k < 8; k++) v[k] = ((b >> k) & 1) ? -0.5f : 0.5f;
    }
#pragma unroll
    for (int k = 0; k < 8; k++) g_roots[idx * 8 + k] = v[k];
}

__global__ void prep_const_kernel(const float* __restrict__ le,
                                  const float* __restrict__ bctl,
                                  const float* __restrict__ bc,
                                  const float* __restrict__ rw1) {
    const float C = 1.0201941611100342f;   // log2(e)/sqrt(2)
    int i = blockIdx.x * blockDim.x + threadIdx.x;
    if (i >= 16384) return;
    float v;
    if (i < 13440) {
        int r = i / 56, c = i - r * 56;
        v = (c < 52) ? le[r * 52 + c] : bctl[r * 4 + (c - 52)];
    } else if (i < 13680) {
        v = bc[i - 13440] + 2.0f * C;
    } else {
        v = rw1[i - 13680];
    }
    g_stage[i] = v;
}

__device__ __forceinline__ float gelu_exact(float x) {
    return 0.5f * x * (1.0f + erff(x * 0.70710678118654752f));
}

__global__ __launch_bounds__(THREADS) void rcpl_kernel(
    const float* __restrict__ obs,   const float* __restrict__ w1, const float* __restrict__ b1,
    const float* __restrict__ w2,    const float* __restrict__ b2,
    const float* __restrict__ le,    const float* __restrict__ rctl,
    const float* __restrict__ ld,
    const float* __restrict__ rb1,
    const float* __restrict__ rw2,   const float* __restrict__ rb2,
    const float* __restrict__ rgate, float* __restrict__ out, int B)
{
    __shared__ float w1S[448];     // [l*14+k]
    __shared__ float b1S[32];
    __shared__ float w2TS[256];    // [l*8+j]  (transposed)
    __shared__ float b2S[8];
    __shared__ float rootsS[1920]; // [j*8+k]
    __shared__ float rw2TS[2704];  // [c*52+k2] (transposed)
    __shared__ float rb1S[52];
    __shared__ float rb2S[52];
    // total 5472 floats = 21888 B

    const float C = 1.0201941611100342f;   // log2(e)/sqrt(2)

    const int t = threadIdx.x;
    for (int i = t; i < 448;  i += THREADS) w1S[i] = w1[i];
    for (int i = t; i < 32;   i += THREADS) b1S[i] = b1[i];
    for (int i = t; i < 256;  i += THREADS) { int l = i >> 3, j = i & 7; w2TS[i] = w2[j * 32 + l]; }
    for (int i = t; i < 8;    i += THREADS) b2S[i] = b2[i];
    for (int i = t; i < 1920; i += THREADS) rootsS[i] = g_roots[i];
    for (int i = t; i < 2704; i += THREADS) { int c = i / 52, k = i - c * 52; rw2TS[i] = rw2[k * 52 + c]; }
    for (int i = t; i < 52;   i += THREADS) rb1S[i] = rb1[i];
    for (int i = t; i < 52;   i += THREADS) rb2S[i] = rb2[i];
    __syncthreads();

    int row = blockIdx.x * THREADS + t;
    if (row >= B) return;

    // ---------------- projection: 14 -> 32 -> 8, fused ----------------
    float x[14];
    {
        const float2* po = reinterpret_cast<const float2*>(obs + (size_t)row * 14);
#pragma unroll
        for (int k = 0; k < 7; k++) { float2 v = po[k]; x[2 * k] = v.x; x[2 * k + 1] = v.y; }
    }
    float q[8];
#pragma unroll
    for (int j = 0; j < 8; j++) q[j] = b2S[j];
#pragma unroll 2
    for (int l = 0; l < 32; l++) {
        float a0 = b1S[l], a1 = 0.f;
        const float2* wr = reinterpret_cast<const float2*>(&w1S[l * 14]);
#pragma unroll
        for (int k = 0; k < 7; k++) { float2 w = wr[k]; a0 = fmaf(x[2 * k], w.x, a0); a1 = fmaf(x[2 * k + 1], w.y, a1); }
        float g = gelu_exact(a0 + a1);
        const float4* wt = reinterpret_cast<const float4*>(&w2TS[l * 8]);
        float4 u0 = wt[0], u1 = wt[1];
        q[0] = fmaf(g, u0.x, q[0]); q[1] = fmaf(g, u0.y, q[1]);
        q[2] = fmaf(g, u0.z, q[2]); q[3] = fmaf(g, u0.w, q[3]);
        q[4] = fmaf(g, u1.x, q[4]); q[5] = fmaf(g, u1.y, q[5]);
        q[6] = fmaf(g, u1.z, q[6]); q[7] = fmaf(g, u1.w, q[7]);
    }
    {
        float n2 = 0.f;
#pragma unroll
        for (int j = 0; j < 8; j++) n2 = fmaf(q[j], q[j], n2);
        float sc = 1.4142135623730951f / fmaxf(sqrtf(n2), 1e-12f);
#pragma unroll
        for (int j = 0; j < 8; j++) q[j] *= sc;
    }

    // ------- fused pass over 240 roots: dot + level-0 argmax + unnormalized softmax GEMM -------
    // emb table + kS come from the constant bank (warp-uniform -> LDCU/UR operands).
    float acc[56];
#pragma unroll
    for (int c = 0; c < 56; c++) acc[c] = 0.f;
    float S = 0.f, bestdot = -1e30f;
    int bestj = 0;
#pragma unroll 2
    for (int j = 0; j < 240; j++) {
        const float4* rp = reinterpret_cast<const float4*>(&rootsS[j * 8]);
        float4 r0 = rp[0], r1 = rp[1];
        float d0 = fmaf(q[1], r0.y, q[0] * r0.x);
        d0 = fmaf(q[2], r0.z, d0); d0 = fmaf(q[3], r0.w, d0);
        float d1 = fmaf(q[5], r1.y, q[4] * r1.x);
        d1 = fmaf(q[6], r1.z, d1); d1 = fmaf(q[7], r1.w, d1);
        float dot = d0 + d1;
        if (dot > bestdot) { bestdot = dot; bestj = j; }   // strict > : first index on ties
        float e = exp2f(fmaf(dot, C, -c_tab[13440 + j]));
        S += e;
        const float4* ep = reinterpret_cast<const float4*>(&c_tab[j * 56]);
#pragma unroll
        for (int c4 = 0; c4 < 14; c4++) {
            float4 ev = ep[c4];
            acc[4 * c4 + 0] = fmaf(e, ev.x, acc[4 * c4 + 0]);
            acc[4 * c4 + 1] = fmaf(e, ev.y, acc[4 * c4 + 1]);
            acc[4 * c4 + 2] = fmaf(e, ev.z, acc[4 * c4 + 2]);
            acc[4 * c4 + 3] = fmaf(e, ev.w, acc[4 * c4 + 3]);
        }
    }
    {
        float invS = 1.0f / S;
#pragma unroll
        for (int c = 0; c < 56; c++) acc[c] *= invS;
    }

    // ---------------- residual E8 quantization, analytic nearest-root decode ----------------
    float res[8];
    {
        const float4* rp = reinterpret_cast<const float4*>(&rootsS[bestj * 8]);
        float4 r0 = rp[0], r1 = rp[1];
        res[0] = fmaf(-2.f, r0.x, q[0]); res[1] = fmaf(-2.f, r0.y, q[1]);
        res[2] = fmaf(-2.f, r0.z, q[2]); res[3] = fmaf(-2.f, r0.w, q[3]);
        res[4] = fmaf(-2.f, r1.x, q[4]); res[5] = fmaf(-2.f, r1.y, q[5]);
        res[6] = fmaf(-2.f, r1.z, q[6]); res[7] = fmaf(-2.f, r1.w, q[7]);
    }
    float decay = expf(ld[0]);
    float invd = 1.0f / decay;
    float s = 2.0f, g = 1.0f;
    for (int lev = 1; lev < 8; lev++) {
        s *= invd; g *= invd;
        float a[8];
#pragma unroll
        for (int k = 0; k < 8; k++) a[k] = fabsf(res[k]);
        int m1 = 0; float v1 = a[0];
#pragma unroll
        for (int k = 1; k < 8; k++) if (a[k] > v1) { v1 = a[k]; m1 = k; }
        int m2 = -1; float v2 = -1.f;
#pragma unroll
        for (int k = 0; k < 8; k++) if (k != m1 && a[k] > v2) { v2 = a[k]; m2 = k; }
        float valA = v1 + v2;
        float sum = 0.f;
#pragma unroll
        for (int k = 0; k < 8; k++) sum += a[k];
        int mask = 0;
#pragma unroll
        for (int k = 0; k < 8; k++) mask |= (res[k] < 0.f) ? (1 << k) : 0;
        int km = 0; float vm = a[0];
#pragma unroll
        for (int k = 1; k < 8; k++) if (a[k] < vm) { vm = a[k]; km = k; }
        int par = __popc(mask) & 1;
        float valB = 0.5f * sum - (par ? vm : 0.f);
        int idx;
        if (valA >= valB) {            // tie -> type A (lower enumeration index)
            int i = (m1 < m2) ? m1 : m2, jj = (m1 < m2) ? m2 : m1;
            int bi = (res[i] < 0.f) ? 1 : 0, bj = (res[jj] < 0.f) ? 1 : 0;
            idx = (7 * i - (i * (i - 1)) / 2 + (jj - i - 1)) * 4 + bi * 2 + bj;
            float di = bi ? -s : s, dj = bj ? -s : s;
#pragma unroll
            for (int k = 0; k < 8; k++) {
                if (k == i)  res[k] -= di;
                if (k == jj) res[k] -= dj;
            }
        } else {
            int bits = par ? (mask ^ (1 << km)) : mask;
            idx = 112 + (bits >> 1);
            float hs = 0.5f * s;
#pragma unroll
            for (int k = 0; k < 8; k++) res[k] -= ((bits >> k) & 1) ? -hs : hs;
        }
        const float4* ep = reinterpret_cast<const float4*>(le + ((size_t)lev * 240 + idx) * 52);
#pragma unroll
        for (int c4 = 0; c4 < 13; c4++) {
            float4 ev = __ldg(&ep[c4]);
            acc[4 * c4 + 0] = fmaf(g, ev.x, acc[4 * c4 + 0]);
            acc[4 * c4 + 1] = fmaf(g, ev.y, acc[4 * c4 + 1]);
            acc[4 * c4 + 2] = fmaf(g, ev.z, acc[4 * c4 + 2]);
            acc[4 * c4 + 3] = fmaf(g, ev.w, acc[4 * c4 + 3]);
        }
        float4 cv = __ldg(reinterpret_cast<const float4*>(rctl + ((size_t)(lev - 1) * 240 + idx) * 4));
        acc[52] = fmaf(g, cv.x, acc[52]); acc[53] = fmaf(g, cv.y, acc[53]);
        acc[54] = fmaf(g, cv.z, acc[54]); acc[55] = fmaf(g, cv.w, acc[55]);
    }

    // ---------------- gated refine MLP ----------------
    // layer 1 weights from constant bank (uniform), layer 2 from smem.
    float r2a[52];
#pragma unroll
    for (int k = 0; k < 52; k++) r2a[k] = 0.f;
#pragma unroll 2
    for (int c = 0; c < 52; c++) {
        float p0 = rb1S[c], p1 = 0.f, p2 = 0.f, p3 = 0.f;
        const float4* wr = reinterpret_cast<const float4*>(&c_tab[13680 + c * 52]);
#pragma unroll
        for (int k4 = 0; k4 < 13; k4++) {
            float4 w = wr[k4];
            p0 = fmaf(acc[4 * k4 + 0], w.x, p0);
            p1 = fmaf(acc[4 * k4 + 1], w.y, p1);
            p2 = fmaf(acc[4 * k4 + 2], w.z, p2);
            p3 = fmaf(acc[4 * k4 + 3], w.w, p3);
        }
        float gv = gelu_exact((p0 + p1) + (p2 + p3));
        const float4* w2r = reinterpret_cast<const float4*>(&rw2TS[c * 52]);
#pragma unroll
        for (int k4 = 0; k4 < 13; k4++) {
            float4 w = w2r[k4];
            r2a[4 * k4 + 0] = fmaf(gv, w.x, r2a[4 * k4 + 0]);
            r2a[4 * k4 + 1] = fmaf(gv, w.y, r2a[4 * k4 + 1]);
            r2a[4 * k4 + 2] = fmaf(gv, w.z, r2a[4 * k4 + 2]);
            r2a[4 * k4 + 3] = fmaf(gv, w.w, r2a[4 * k4 + 3]);
        }
    }
    {
        float gate = 1.0f / (1.0f + expf(-rgate[0]));
#pragma unroll
        for (int c = 0; c < 52; c++) acc[c] = fmaf(gate, r2a[c] + rb2S[c], acc[c]);
    }

    // ---------------- store [56] ----------------
    float4* op = reinterpret_cast<float4*>(out + (size_t)row * 56);
#pragma unroll
    for (int c4 = 0; c4 < 14; c4++) {
        float4 v;
        v.x = acc[4 * c4 + 0]; v.y = acc[4 * c4 + 1];
        v.z = acc[4 * c4 + 2]; v.w = acc[4 * c4 + 3];
        op[c4] = v;
    }
}

extern "C" void kernel_launch(void* const* d_in, const int* in_sizes, int n_in,
                              void* d_out, int out_size) {
    const float* obs   = (const float*)d_in[0];
    const float* w1    = (const float*)d_in[1];
    const float* b1    = (const float*)d_in[2];
    const float* w2    = (const float*)d_in[3];
    const float* b2    = (const float*)d_in[4];
    const float* le    = (const float*)d_in[5];
    const float* bctl  = (const float*)d_in[6];
    const float* rctl  = (const float*)d_in[7];
    const float* bc    = (const float*)d_in[8];
    const float* ld    = (const float*)d_in[9];
    const float* rw1   = (const float*)d_in[10];
    const float* rb1   = (const float*)d_in[11];
    const float* rw2   = (const float*)d_in[12];
    const float* rb2   = (const float*)d_in[13];
    const float* rgate = (const float*)d_in[14];
    float* out = (float*)d_out;

    int B = in_sizes[0] / 14;

    init_roots_kernel<<<1, 256>>>();
    prep_const_kernel<<<64, 256>>>(le, bctl, bc, rw1);

    void* c_addr = nullptr;
    void* s_addr = nullptr;
    cudaGetSymbolAddress(&c_addr, c_tab);
    cudaGetSymbolAddress(&s_addr, g_stage);
    cudaMemcpyAsync(c_addr, s_addr, 16384 * sizeof(float), cudaMemcpyDeviceToDevice, 0);

    rcpl_kernel<<<(B + THREADS - 1) / THREADS, THREADS>>>(
        obs, w1, b1, w2, b2, le, rctl, ld, rb1, rw2, rb2, rgate, out, B);
}

// round 5
// speedup vs baseline: 1.2821x; 1.1613x over previous
#include <cuda_runtime.h>
#include <math.h>

#define TPB 128
#define ROWS_PER_BLOCK 256

// ---------------- constant bank ----------------
// [0     : 8640)  emb cols 20..55  [j*36 + (c-20)]  (level0 emb || base_ctrl)
// [8640  : 8880)  kbc [j]  = bc[j] + 2*C
// [8880  : 11584) rw1 [c*52 + k]
#define EMBC_OFF 0
#define KBC_OFF  8640
#define RW1_OFF  8880
#define CTAB_N   11584
__constant__ __align__(16) float c_tab[CTAB_N];
__device__ __align__(16) float g_stage[CTAB_N];
__device__ __align__(16) float g_roots[240 * 8];

typedef unsigned long long u64;

__device__ __forceinline__ u64 pk(float x, float y) {
    u64 r; asm("mov.b64 %0,{%1,%2};" : "=l"(r) : "f"(x), "f"(y)); return r;
}
__device__ __forceinline__ void upk(float& x, float& y, u64 v) {
    asm("mov.b64 {%0,%1},%2;" : "=f"(x), "=f"(y) : "l"(v));
}
__device__ __forceinline__ u64 f2fma(u64 a, u64 b, u64 c) {
    u64 d; asm("fma.rn.f32x2 %0,%1,%2,%3;" : "=l"(d) : "l"(a), "l"(b), "l"(c)); return d;
}
__device__ __forceinline__ u64 f2mul(u64 a, u64 b) {
    u64 d; asm("mul.rn.f32x2 %0,%1,%2;" : "=l"(d) : "l"(a), "l"(b)); return d;
}
__device__ __forceinline__ u64 f2add(u64 a, u64 b) {
    u64 d; asm("add.rn.f32x2 %0,%1,%2;" : "=l"(d) : "l"(a), "l"(b)); return d;
}

__global__ void init_roots_kernel() {
    int idx = blockIdx.x * blockDim.x + threadIdx.x;
    if (idx >= 240) return;
    float v[8];
#pragma unroll
    for (int k = 0; k < 8; k++) v[k] = 0.f;
    if (idx < 112) {
        int p = idx >> 2, sb = idx & 3;
        int i = 0, rem = p;
        while (rem >= 7 - i) { rem -= (7 - i); i++; }
        int j = i + 1 + rem;
        v[i] = (sb & 2) ? -1.f : 1.f;
        v[j] = (sb & 1) ? -1.f : 1.f;
    } else {
        int b = (idx - 112) << 1;
        if (__popc(b) & 1) b |= 1;
#pragma unroll
        for (int k = 0; k < 8; k++) v[k] = ((b >> k) & 1) ? -0.5f : 0.5f;
    }
#pragma unroll
    for (int k = 0; k < 8; k++) g_roots[idx * 8 + k] = v[k];
}

__global__ void prep_const_kernel(const float* __restrict__ le,
                                  const float* __restrict__ bctl,
                                  const float* __restrict__ bc,
                                  const float* __restrict__ rw1) {
    const float C = 1.0201941611100342f;   // log2(e)/sqrt(2)
    int i = blockIdx.x * blockDim.x + threadIdx.x;
    if (i >= CTAB_N) return;
    float v;
    if (i < KBC_OFF) {
        int j = i / 36, c = i - j * 36 + 20;
        v = (c < 52) ? le[j * 52 + c] : bctl[j * 4 + (c - 52)];
    } else if (i < RW1_OFF) {
        v = bc[i - KBC_OFF] + 2.0f * C;
    } else {
        v = rw1[i - RW1_OFF];
    }
    g_stage[i] = v;
}

__device__ __forceinline__ float gelu_exact(float x) {
    return 0.5f * x * (1.0f + erff(x * 0.70710678118654752f));
}

// Analytic nearest-E8-root: returns reference enumeration index, subtracts root*s in place.
__device__ __forceinline__ int decode_step(float res[8], float s) {
    float a[8];
#pragma unroll
    for (int k = 0; k < 8; k++) a[k] = fabsf(res[k]);
    int m1 = 0; float v1 = a[0];
#pragma unroll
    for (int k = 1; k < 8; k++) if (a[k] > v1) { v1 = a[k]; m1 = k; }
    int m2 = -1; float v2 = -1.f;
#pragma unroll
    for (int k = 0; k < 8; k++) if (k != m1 && a[k] > v2) { v2 = a[k]; m2 = k; }
    float valA = v1 + v2;
    float sum = 0.f;
#pragma unroll
    for (int k = 0; k < 8; k++) sum += a[k];
    int mask = 0;
#pragma unroll
    for (int k = 0; k < 8; k++) mask |= (res[k] < 0.f) ? (1 << k) : 0;
    int km = 0; float vm = a[0];
#pragma unroll
    for (int k = 1; k < 8; k++) if (a[k] < vm) { vm = a[k]; km = k; }
    int par = __popc(mask) & 1;
    float valB = 0.5f * sum - (par ? vm : 0.f);
    int idx;
    if (valA >= valB) {            // tie -> type A (lower enumeration index)
        int i = (m1 < m2) ? m1 : m2, jj = (m1 < m2) ? m2 : m1;
        int bi = (res[i] < 0.f) ? 1 : 0, bj = (res[jj] < 0.f) ? 1 : 0;
        idx = (7 * i - (i * (i - 1)) / 2 + (jj - i - 1)) * 4 + bi * 2 + bj;
        float di = bi ? -s : s, dj = bj ? -s : s;
#pragma unroll
        for (int k = 0; k < 8; k++) {
            if (k == i)  res[k] -= di;
            if (k == jj) res[k] -= dj;
        }
    } else {
        int bits = par ? (mask ^ (1 << km)) : mask;
        idx = 112 + (bits >> 1);
        float hs = 0.5f * s;
#pragma unroll
        for (int k = 0; k < 8; k++) res[k] -= ((bits >> k) & 1) ? -hs : hs;
    }
    return idx;
}

__global__ __launch_bounds__(TPB, 2) void rcpl_kernel(
    const float* __restrict__ obs,   const float* __restrict__ w1, const float* __restrict__ b1,
    const float* __restrict__ w2,    const float* __restrict__ b2,
    const float* __restrict__ le,    const float* __restrict__ rctl,
    const float* __restrict__ ld,
    const float* __restrict__ rb1,
    const float* __restrict__ rw2,   const float* __restrict__ rb2,
    const float* __restrict__ rgate, float* __restrict__ out, int B)
{
    __shared__ __align__(16) float rootsS[1920];   // [j*8+k]
    __shared__ __align__(16) float embS20[4800];   // [j*20+c] emb cols 0..19
    __shared__ __align__(16) float rw2TS[2704];    // [c*52+k2] (transposed)
    __shared__ __align__(16) float w1S[448];       // [l*14+k]
    __shared__ __align__(16) float w2TS[256];      // [l*8+j]  (transposed)
    __shared__ float b1S[32];
    __shared__ float b2S[8];
    __shared__ __align__(16) float rb2S[52];
    __shared__ float rb1S[52];

    const float C = 1.0201941611100342f;   // log2(e)/sqrt(2)
    const int t = threadIdx.x;

    for (int i = t; i < 1920; i += TPB) rootsS[i] = g_roots[i];
    for (int i = t; i < 4800; i += TPB) { int j = i / 20, c = i - j * 20; embS20[i] = le[j * 52 + c]; }
    for (int i = t; i < 2704; i += TPB) { int c = i / 52, k = i - c * 52; rw2TS[i] = rw2[k * 52 + c]; }
    for (int i = t; i < 448;  i += TPB) w1S[i] = w1[i];
    for (int i = t; i < 256;  i += TPB) { int l = i >> 3, j = i & 7; w2TS[i] = w2[j * 32 + l]; }
    for (int i = t; i < 32;   i += TPB) b1S[i] = b1[i];
    for (int i = t; i < 8;    i += TPB) b2S[i] = b2[i];
    for (int i = t; i < 52;   i += TPB) { rb1S[i] = rb1[i]; rb2S[i] = rb2[i]; }
    __syncthreads();

    int r0 = blockIdx.x * ROWS_PER_BLOCK + t;
    if (r0 >= B) return;
    int r1 = r0 + TPB;
    bool has1 = (r1 < B);
    int r1c = has1 ? r1 : r0;

    // ---------------- projection: 14 -> 32 -> 8 for both rows (shared weight loads) ----------
    float x0[14], x1[14];
    {
        const float2* p0 = reinterpret_cast<const float2*>(obs + (size_t)r0 * 14);
        const float2* p1 = reinterpret_cast<const float2*>(obs + (size_t)r1c * 14);
#pragma unroll
        for (int k = 0; k < 7; k++) {
            float2 v0 = p0[k], v1 = p1[k];
            x0[2 * k] = v0.x; x0[2 * k + 1] = v0.y;
            x1[2 * k] = v1.x; x1[2 * k + 1] = v1.y;
        }
    }
    float q0[8], q1[8];
#pragma unroll
    for (int j = 0; j < 8; j++) { q0[j] = b2S[j]; q1[j] = b2S[j]; }
#pragma unroll 2
    for (int l = 0; l < 32; l++) {
        float h0 = b1S[l], h1 = b1S[l];
        const float2* wr = reinterpret_cast<const float2*>(&w1S[l * 14]);
#pragma unroll
        for (int k = 0; k < 7; k++) {
            float2 w = wr[k];
            h0 = fmaf(x0[2 * k], w.x, h0); h0 = fmaf(x0[2 * k + 1], w.y, h0);
            h1 = fmaf(x1[2 * k], w.x, h1); h1 = fmaf(x1[2 * k + 1], w.y, h1);
        }
        float g0 = gelu_exact(h0), g1 = gelu_exact(h1);
        const float4* wt = reinterpret_cast<const float4*>(&w2TS[l * 8]);
        float4 u0 = wt[0], u1 = wt[1];
        q0[0] = fmaf(g0, u0.x, q0[0]); q0[1] = fmaf(g0, u0.y, q0[1]);
        q0[2] = fmaf(g0, u0.z, q0[2]); q0[3] = fmaf(g0, u0.w, q0[3]);
        q0[4] = fmaf(g0, u1.x, q0[4]); q0[5] = fmaf(g0, u1.y, q0[5]);
        q0[6] = fmaf(g0, u1.z, q0[6]); q0[7] = fmaf(g0, u1.w, q0[7]);
        q1[0] = fmaf(g1, u0.x, q1[0]); q1[1] = fmaf(g1, u0.y, q1[1]);
        q1[2] = fmaf(g1, u0.z, q1[2]); q1[3] = fmaf(g1, u0.w, q1[3]);
        q1[4] = fmaf(g1, u1.x, q1[4]); q1[5] = fmaf(g1, u1.y, q1[5]);
        q1[6] = fmaf(g1, u1.z, q1[6]); q1[7] = fmaf(g1, u1.w, q1[7]);
    }
    {
        float n0 = 0.f, n1 = 0.f;
#pragma unroll
        for (int j = 0; j < 8; j++) { n0 = fmaf(q0[j], q0[j], n0); n1 = fmaf(q1[j], q1[j], n1); }
        float s0 = 1.4142135623730951f / fmaxf(sqrtf(n0), 1e-12f);
        float s1 = 1.4142135623730951f / fmaxf(sqrtf(n1), 1e-12f);
#pragma unroll
        for (int j = 0; j < 8; j++) { q0[j] *= s0; q1[j] *= s1; }
    }

    u64 qp0[4], qp1[4];
#pragma unroll
    for (int k = 0; k < 4; k++) { qp0[k] = pk(q0[2 * k], q0[2 * k + 1]); qp1[k] = pk(q1[2 * k], q1[2 * k + 1]); }

    // ------- fused 240-root pass: softmax-weighted table accumulate (both rows) -------
    u64 acc0[28], acc1[28];
#pragma unroll
    for (int k = 0; k < 28; k++) { acc0[k] = 0ull; acc1[k] = 0ull; }
    float S0 = 0.f, S1 = 0.f;
    for (int j = 0; j < 240; j++) {
        const u64* rp = reinterpret_cast<const u64*>(&rootsS[j * 8]);
        u64 rr0 = rp[0], rr1 = rp[1], rr2 = rp[2], rr3 = rp[3];
        u64 d0 = f2mul(qp0[0], rr0);
        d0 = f2fma(qp0[1], rr1, d0); d0 = f2fma(qp0[2], rr2, d0); d0 = f2fma(qp0[3], rr3, d0);
        u64 d1 = f2mul(qp1[0], rr0);
        d1 = f2fma(qp1[1], rr1, d1); d1 = f2fma(qp1[2], rr2, d1); d1 = f2fma(qp1[3], rr3, d1);
        float dl, dh; upk(dl, dh, d0); float dot0 = dl + dh;
        float el, eh; upk(el, eh, d1); float dot1 = el + eh;
        float kbc = c_tab[KBC_OFF + j];
        float e0 = exp2f(fmaf(dot0, C, -kbc));
        float e1 = exp2f(fmaf(dot1, C, -kbc));
        S0 += e0; S1 += e1;
        u64 e0b = pk(e0, e0), e1b = pk(e1, e1);
        const ulonglong2* es = reinterpret_cast<const ulonglong2*>(&embS20[j * 20]);
#pragma unroll
        for (int k = 0; k < 5; k++) {
            ulonglong2 w = es[k];
            acc0[2 * k]     = f2fma(e0b, w.x, acc0[2 * k]);
            acc0[2 * k + 1] = f2fma(e0b, w.y, acc0[2 * k + 1]);
            acc1[2 * k]     = f2fma(e1b, w.x, acc1[2 * k]);
            acc1[2 * k + 1] = f2fma(e1b, w.y, acc1[2 * k + 1]);
        }
        const ulonglong2* ec = reinterpret_cast<const ulonglong2*>(&c_tab[EMBC_OFF + j * 36]);
#pragma unroll
        for (int k = 0; k < 9; k++) {
            ulonglong2 w = ec[k];
            acc0[10 + 2 * k]     = f2fma(e0b, w.x, acc0[10 + 2 * k]);
            acc0[10 + 2 * k + 1] = f2fma(e0b, w.y, acc0[10 + 2 * k + 1]);
            acc1[10 + 2 * k]     = f2fma(e1b, w.x, acc1[10 + 2 * k]);
            acc1[10 + 2 * k + 1] = f2fma(e1b, w.y, acc1[10 + 2 * k + 1]);
        }
    }
    {
        float i0 = 1.0f / S0, i1 = 1.0f / S1;
        u64 iv0 = pk(i0, i0), iv1 = pk(i1, i1);
#pragma unroll
        for (int k = 0; k < 28; k++) { acc0[k] = f2mul(acc0[k], iv0); acc1[k] = f2mul(acc1[k], iv1); }
    }

    // ---------------- residual E8 quantization: analytic decode, all 8 levels ----------------
    float invd = expf(-ld[0]);
    int i0s[8], i1s[8];
    {
        float res0[8], res1[8];
#pragma unroll
        for (int k = 0; k < 8; k++) { res0[k] = q0[k]; res1[k] = q1[k]; }
        float s = 2.f;
#pragma unroll
        for (int lev = 0; lev < 8; lev++) {
            i0s[lev] = decode_step(res0, s);
            i1s[lev] = decode_step(res1, s);
            s *= invd;
        }
    }
    // Gathers for levels 1..7 (level 0 handled by the softmax above).
    // 13 ulonglong2 = 52 floats = emb cols 0..51 -> acc[0..25]; ctrl -> acc[26..27].
    {
        float gg = invd;
#pragma unroll
        for (int lev = 1; lev < 8; lev++) {
            u64 gb = pk(gg, gg);
            const ulonglong2* e0p = reinterpret_cast<const ulonglong2*>(le + ((size_t)lev * 240 + i0s[lev]) * 52);
            const ulonglong2* e1p = reinterpret_cast<const ulonglong2*>(le + ((size_t)lev * 240 + i1s[lev]) * 52);
#pragma unroll
            for (int k = 0; k < 13; k++) {
                ulonglong2 w0 = e0p[k], w1v = e1p[k];
                acc0[2 * k]     = f2fma(gb, w0.x, acc0[2 * k]);
                acc0[2 * k + 1] = f2fma(gb, w0.y, acc0[2 * k + 1]);
                acc1[2 * k]     = f2fma(gb, w1v.x, acc1[2 * k]);
                acc1[2 * k + 1] = f2fma(gb, w1v.y, acc1[2 * k + 1]);
            }
            const u64* c0p = reinterpret_cast<const u64*>(rctl + ((size_t)(lev - 1) * 240 + i0s[lev]) * 4);
            const u64* c1p = reinterpret_cast<const u64*>(rctl + ((size_t)(lev - 1) * 240 + i1s[lev]) * 4);
            acc0[26] = f2fma(gb, c0p[0], acc0[26]); acc0[27] = f2fma(gb, c0p[1], acc0[27]);
            acc1[26] = f2fma(gb, c1p[0], acc1[26]); acc1[27] = f2fma(gb, c1p[1], acc1[27]);
            gg *= invd;
        }
    }

    // ---------------- gated refine MLP (per row, reusing r2a regs) ----------------
    float gate = 1.0f / (1.0f + expf(-rgate[0]));
    u64 gateb = pk(gate, gate);
#pragma unroll
    for (int r = 0; r < 2; r++) {
        u64* acc = r ? acc1 : acc0;
        u64 r2a[26];
#pragma unroll
        for (int k = 0; k < 26; k++) r2a[k] = 0ull;
#pragma unroll 2
        for (int c = 0; c < 52; c++) {
            u64 p = pk(rb1S[c], 0.f);
            const ulonglong2* wr = reinterpret_cast<const ulonglong2*>(&c_tab[RW1_OFF + c * 52]);
#pragma unroll
            for (int k = 0; k < 13; k++) {
                ulonglong2 w = wr[k];
                p = f2fma(acc[2 * k], w.x, p);
                p = f2fma(acc[2 * k + 1], w.y, p);
            }
            float pl, ph; upk(pl, ph, p);
            float gv = gelu_exact(pl + ph);
            u64 gvb = pk(gv, gv);
            const ulonglong2* w2r = reinterpret_cast<const ulonglong2*>(&rw2TS[c * 52]);
#pragma unroll
            for (int k = 0; k < 13; k++) {
                ulonglong2 w = w2r[k];
                r2a[2 * k]     = f2fma(gvb, w.x, r2a[2 * k]);
                r2a[2 * k + 1] = f2fma(gvb, w.y, r2a[2 * k + 1]);
            }
        }
        const u64* rb2p = reinterpret_cast<const u64*>(rb2S);
#pragma unroll
        for (int k = 0; k < 26; k++)
            acc[k] = f2fma(gateb, f2add(r2a[k], rb2p[k]), acc[k]);
    }

    // ---------------- stores ----------------
    {
        float4* op = reinterpret_cast<float4*>(out + (size_t)r0 * 56);
#pragma unroll
        for (int c4 = 0; c4 < 14; c4++) {
            float4 v;
            upk(v.x, v.y, acc0[2 * c4]); upk(v.z, v.w, acc0[2 * c4 + 1]);
            op[c4] = v;
        }
    }
    if (has1) {
        float4* op = reinterpret_cast<float4*>(out + (size_t)r1 * 56);
#pragma unroll
        for (int c4 = 0; c4 < 14; c4++) {
            float4 v;
            upk(v.x, v.y, acc1[2 * c4]); upk(v.z, v.w, acc1[2 * c4 + 1]);
            op[c4] = v;
        }
    }
}

extern "C" void kernel_launch(void* const* d_in, const int* in_sizes, int n_in,
                              void* d_out, int out_size) {
    const float* obs   = (const float*)d_in[0];
    const float* w1    = (const float*)d_in[1];
    const float* b1    = (const float*)d_in[2];
    const float* w2    = (const float*)d_in[3];
    const float* b2    = (const float*)d_in[4];
    const float* le    = (const float*)d_in[5];
    const float* bctl  = (const float*)d_in[6];
    const float* rctl  = (const float*)d_in[7];
    const float* bc    = (const float*)d_in[8];
    const float* ld    = (const float*)d_in[9];
    const float* rw1   = (const float*)d_in[10];
    const float* rb1   = (const float*)d_in[11];
    const float* rw2   = (const float*)d_in[12];
    const float* rb2   = (const float*)d_in[13];
    const float* rgate = (const float*)d_in[14];
    float* out = (float*)d_out;

    int B = in_sizes[0] / 14;

    init_roots_kernel<<<1, 256>>>();
    prep_const_kernel<<<(CTAB_N + 255) / 256, 256>>>(le, bctl, bc, rw1);

    void* c_addr = nullptr;
    void* s_addr = nullptr;
    cudaGetSymbolAddress(&c_addr, c_tab);
    cudaGetSymbolAddress(&s_addr, g_stage);
    cudaMemcpyAsync(c_addr, s_addr, CTAB_N * sizeof(float), cudaMemcpyDeviceToDevice, 0);

    int blocks = (B + ROWS_PER_BLOCK - 1) / ROWS_PER_BLOCK;
    rcpl_kernel<<<blocks, TPB>>>(
        obs, w1, b1, w2, b2, le, rctl, ld, rb1, rw2, rb2, rgate, out, B);
}